// round 1
// baseline (speedup 1.0000x reference)
#include <cuda_runtime.h>
#include <math.h>
#include <stdint.h>

#define DM   512
#define NH   8
#define HD   64
#define DFF  2048
#define BATCH 2
#define SEQ  4096
#define NR   (BATCH*SEQ)   // 8192 rows

// ---------------- scratch (device globals: no allocation in kernel_launch) ----
__device__ float g_Q[BATCH*NH*SEQ*HD];   // 16 MB  [bh, s, d]
__device__ float g_K[BATCH*NH*SEQ*HD];   // 16 MB
__device__ float g_V[BATCH*NH*SEQ*HD];   // 16 MB
__device__ float g_C[NR*DM];             // 16 MB  attention context [n, h*64+d]
__device__ float g_Y[NR*DM];             // 16 MB  pre-LN sums
__device__ float g_X1[NR*DM];            // 16 MB  LN1 output (residual source)
__device__ float g_H[(size_t)NR*DFF];    // 64 MB  FFN hidden

// =======================================================================
// GEMM: C[M,N] = A[M,K] @ Bw[N,K]^T + bias[N] (+ add[M,N]) (relu)
// 128x128 tile, BK=16, 256 threads, 8x8 microtile, double-buffered smem.
// SCATTER=true: write to [(b*8+h)*4096+s]*64+d layout (QKV path).
// =======================================================================
template<bool SCATTER>
__global__ __launch_bounds__(256, 2)
void gemm_kernel(const float* __restrict__ A, const float* __restrict__ Bw,
                 const float* __restrict__ bias, const float* __restrict__ add,
                 float* __restrict__ C, int M, int N, int K, int relu)
{
    __shared__ float As[2][16][132];
    __shared__ float Bs[2][16][132];

    const int tid = threadIdx.x;
    const int bm  = blockIdx.y << 7;
    const int bn  = blockIdx.x << 7;
    const int tr  = (tid >> 4) << 3;   // tile row base of 8x8 microtile
    const int tc  = (tid & 15) << 3;   // tile col base
    const int row0 = tid >> 2;         // 0..63 (and +64)
    const int kq   = (tid & 3) << 2;   // 0,4,8,12

    const float* Ap0 = A  + (size_t)(bm + row0) * K + kq;
    const float* Ap1 = Ap0 + (size_t)64 * K;
    const float* Bp0 = Bw + (size_t)(bn + row0) * K + kq;
    const float* Bp1 = Bp0 + (size_t)64 * K;

    float acc[8][8];
#pragma unroll
    for (int i = 0; i < 8; i++)
#pragma unroll
        for (int j = 0; j < 8; j++) acc[i][j] = 0.f;

    float4 ra0 = *(const float4*)(Ap0);
    float4 ra1 = *(const float4*)(Ap1);
    float4 rb0 = *(const float4*)(Bp0);
    float4 rb1 = *(const float4*)(Bp1);

    const int KT = K >> 4;
    for (int kt = 0; kt < KT; kt++) {
        const int cur = kt & 1;
        // stage registers -> smem (transposed: [k][m])
        As[cur][kq+0][row0]    = ra0.x; As[cur][kq+1][row0]    = ra0.y;
        As[cur][kq+2][row0]    = ra0.z; As[cur][kq+3][row0]    = ra0.w;
        As[cur][kq+0][row0+64] = ra1.x; As[cur][kq+1][row0+64] = ra1.y;
        As[cur][kq+2][row0+64] = ra1.z; As[cur][kq+3][row0+64] = ra1.w;
        Bs[cur][kq+0][row0]    = rb0.x; Bs[cur][kq+1][row0]    = rb0.y;
        Bs[cur][kq+2][row0]    = rb0.z; Bs[cur][kq+3][row0]    = rb0.w;
        Bs[cur][kq+0][row0+64] = rb1.x; Bs[cur][kq+1][row0+64] = rb1.y;
        Bs[cur][kq+2][row0+64] = rb1.z; Bs[cur][kq+3][row0+64] = rb1.w;
        __syncthreads();

        if (kt + 1 < KT) {
            const int off = (kt + 1) << 4;
            ra0 = *(const float4*)(Ap0 + off);
            ra1 = *(const float4*)(Ap1 + off);
            rb0 = *(const float4*)(Bp0 + off);
            rb1 = *(const float4*)(Bp1 + off);
        }

#pragma unroll
        for (int k = 0; k < 16; k++) {
            float4 A0 = *(const float4*)&As[cur][k][tr];
            float4 A1 = *(const float4*)&As[cur][k][tr+4];
            float4 B0 = *(const float4*)&Bs[cur][k][tc];
            float4 B1 = *(const float4*)&Bs[cur][k][tc+4];
            float av[8] = {A0.x,A0.y,A0.z,A0.w,A1.x,A1.y,A1.z,A1.w};
            float bv[8] = {B0.x,B0.y,B0.z,B0.w,B1.x,B1.y,B1.z,B1.w};
#pragma unroll
            for (int i = 0; i < 8; i++)
#pragma unroll
                for (int j = 0; j < 8; j++)
                    acc[i][j] += av[i] * bv[j];
        }
        // safe single-sync double buffer: next store goes to the other buffer,
        // whose last reads preceded the sync above for every thread.
    }

    // epilogue
#pragma unroll
    for (int i = 0; i < 8; i++) {
        const int gr = bm + tr + i;
#pragma unroll
        for (int j4 = 0; j4 < 2; j4++) {
            const int gc = bn + tc + (j4 << 2);
            float4 v;
            v.x = acc[i][j4*4+0] + bias[gc+0];
            v.y = acc[i][j4*4+1] + bias[gc+1];
            v.z = acc[i][j4*4+2] + bias[gc+2];
            v.w = acc[i][j4*4+3] + bias[gc+3];
            if (add) {
                float4 ad = *(const float4*)(add + (size_t)gr * N + gc);
                v.x += ad.x; v.y += ad.y; v.z += ad.z; v.w += ad.w;
            }
            if (relu) {
                v.x = fmaxf(v.x, 0.f); v.y = fmaxf(v.y, 0.f);
                v.z = fmaxf(v.z, 0.f); v.w = fmaxf(v.w, 0.f);
            }
            if (SCATTER) {
                const int b = gr >> 12;        // /4096
                const int s = gr & 4095;
                const int h = gc >> 6;
                const int d = gc & 63;
                *(float4*)(C + ((((size_t)b*NH + h)*SEQ + s) << 6) + d) = v;
            } else {
                *(float4*)(C + (size_t)gr * N + gc) = v;
            }
        }
    }
}

// =======================================================================
// Flash attention (fp32). One CTA = 64 queries of one (b,h).
// smem tiles 64x64 with chunk-XOR swizzle: element (r,c) lives at
// r*68 + (((c>>2) ^ ((r>>2)&15))<<2) + (c&3)  -> all float4 accesses stay
// aligned, column-strided row accesses are spread across banks.
// Thread map: warp w owns rows w*8..w*8+7; lane = (lr=lane>>4, lc=lane&15);
// 4x4 microtile at rows i0=w*8+lr*4, cols c0=lc*4. Row softmax stats are
// reduced over the 16 lane_c lanes with shfl_xor (offsets 1,2,4,8).
// =======================================================================
__device__ __forceinline__ int sidx(int r, int c) {
    return r * 68 + ((((c >> 2) ^ ((r >> 2) & 15)) << 2) | (c & 3));
}

__global__ __launch_bounds__(256, 2)
void attn_kernel(const float* __restrict__ Q, const float* __restrict__ Kt,
                 const float* __restrict__ Vt, const float* __restrict__ mask,
                 float* __restrict__ ctx)
{
    extern __shared__ float smdyn[];
    float* Qs = smdyn;                 // 64*68
    float* Ks = smdyn + 4352;
    float* Vs = smdyn + 8704;
    float* Ps = smdyn + 13056;

    const int h  = blockIdx.x;
    const int qt = blockIdx.y;
    const int b  = blockIdx.z;
    const int tid  = threadIdx.x;
    const int w    = tid >> 5;
    const int lane = tid & 31;
    const int lr   = lane >> 4;
    const int lc   = lane & 15;
    const int i0   = (w << 3) + (lr << 2);
    const int c0   = lc << 2;

    const size_t base = ((size_t)(b * NH + h)) * SEQ * HD;
    const float* Qp = Q  + base + ((size_t)qt << 6) * HD;
    const float* Kp = Kt + base;
    const float* Vp = Vt + base;
    const float* Mp = mask + (size_t)b * SEQ * SEQ + ((size_t)(qt << 6)) * SEQ;

    // load Q tile
#pragma unroll
    for (int u = 0; u < 4; u++) {
        const int f = tid + (u << 8);
        const int row = f >> 4;
        const int d4  = (f & 15) << 2;
        *(float4*)&Qs[sidx(row, d4)] = *(const float4*)(Qp + row * HD + d4);
    }

    float m[4], l[4], o[4][4];
#pragma unroll
    for (int i = 0; i < 4; i++) {
        m[i] = -1e30f; l[i] = 0.f;
#pragma unroll
        for (int j = 0; j < 4; j++) o[i][j] = 0.f;
    }
    __syncthreads();

    for (int kt = 0; kt < SEQ / 64; kt++) {
        // load K,V tiles (previous iteration's reads were fenced by loop-end sync)
#pragma unroll
        for (int u = 0; u < 4; u++) {
            const int f = tid + (u << 8);
            const int row = f >> 4;
            const int d4  = (f & 15) << 2;
            const size_t g = ((size_t)(kt << 6) + row) * HD + d4;
            *(float4*)&Ks[sidx(row, d4)] = *(const float4*)(Kp + g);
            *(float4*)&Vs[sidx(row, d4)] = *(const float4*)(Vp + g);
        }
        __syncthreads();

        // ---- S = Q K^T (4x4 per thread) ----
        float s[4][4];
#pragma unroll
        for (int i = 0; i < 4; i++)
#pragma unroll
            for (int j = 0; j < 4; j++) s[i][j] = 0.f;

#pragma unroll
        for (int d4 = 0; d4 < 64; d4 += 4) {
            float4 qv[4], kv[4];
#pragma unroll
            for (int ii = 0; ii < 4; ii++) qv[ii] = *(const float4*)&Qs[sidx(i0 + ii, d4)];
#pragma unroll
            for (int jj = 0; jj < 4; jj++) kv[jj] = *(const float4*)&Ks[sidx(c0 + jj, d4)];
#pragma unroll
            for (int ii = 0; ii < 4; ii++) {
                s[ii][0] += qv[ii].x*kv[0].x + qv[ii].y*kv[0].y + qv[ii].z*kv[0].z + qv[ii].w*kv[0].w;
                s[ii][1] += qv[ii].x*kv[1].x + qv[ii].y*kv[1].y + qv[ii].z*kv[1].z + qv[ii].w*kv[1].w;
                s[ii][2] += qv[ii].x*kv[2].x + qv[ii].y*kv[2].y + qv[ii].z*kv[2].z + qv[ii].w*kv[2].w;
                s[ii][3] += qv[ii].x*kv[3].x + qv[ii].y*kv[3].y + qv[ii].z*kv[3].z + qv[ii].w*kv[3].w;
            }
        }

        // ---- scale + mask + online softmax ----
        float tm[4];
#pragma unroll
        for (int i = 0; i < 4; i++) {
            const float4 mv = *(const float4*)(Mp + (size_t)(i0 + i) * SEQ + (kt << 6) + c0);
            s[i][0] = s[i][0] * 0.125f + (1.f - mv.x) * -1e9f;
            s[i][1] = s[i][1] * 0.125f + (1.f - mv.y) * -1e9f;
            s[i][2] = s[i][2] * 0.125f + (1.f - mv.z) * -1e9f;
            s[i][3] = s[i][3] * 0.125f + (1.f - mv.w) * -1e9f;
            float t = fmaxf(fmaxf(s[i][0], s[i][1]), fmaxf(s[i][2], s[i][3]));
#pragma unroll
            for (int off = 1; off < 16; off <<= 1)
                t = fmaxf(t, __shfl_xor_sync(0xffffffffu, t, off));
            tm[i] = t;
        }
#pragma unroll
        for (int i = 0; i < 4; i++) {
            const float mn = fmaxf(m[i], tm[i]);
            const float sc = __expf(m[i] - mn);
            m[i] = mn;
            float p0 = __expf(s[i][0] - mn);
            float p1 = __expf(s[i][1] - mn);
            float p2 = __expf(s[i][2] - mn);
            float p3 = __expf(s[i][3] - mn);
            s[i][0] = p0; s[i][1] = p1; s[i][2] = p2; s[i][3] = p3;
            float t = p0 + p1 + p2 + p3;
#pragma unroll
            for (int off = 1; off < 16; off <<= 1)
                t += __shfl_xor_sync(0xffffffffu, t, off);
            l[i] = l[i] * sc + t;
            o[i][0] *= sc; o[i][1] *= sc; o[i][2] *= sc; o[i][3] *= sc;
        }

        // ---- write P ----
#pragma unroll
        for (int i = 0; i < 4; i++)
            *(float4*)&Ps[sidx(i0 + i, c0)] = make_float4(s[i][0], s[i][1], s[i][2], s[i][3]);
        __syncthreads();

        // ---- O += P V ----
#pragma unroll
        for (int j4 = 0; j4 < 64; j4 += 4) {
            float4 pv[4], vv[4];
#pragma unroll
            for (int ii = 0; ii < 4; ii++) pv[ii] = *(const float4*)&Ps[sidx(i0 + ii, j4)];
#pragma unroll
            for (int jj = 0; jj < 4; jj++) vv[jj] = *(const float4*)&Vs[sidx(j4 + jj, c0)];
#pragma unroll
            for (int ii = 0; ii < 4; ii++) {
                o[ii][0] += pv[ii].x*vv[0].x + pv[ii].y*vv[1].x + pv[ii].z*vv[2].x + pv[ii].w*vv[3].x;
                o[ii][1] += pv[ii].x*vv[0].y + pv[ii].y*vv[1].y + pv[ii].z*vv[2].y + pv[ii].w*vv[3].y;
                o[ii][2] += pv[ii].x*vv[0].z + pv[ii].y*vv[1].z + pv[ii].z*vv[2].z + pv[ii].w*vv[3].z;
                o[ii][3] += pv[ii].x*vv[0].w + pv[ii].y*vv[1].w + pv[ii].z*vv[2].w + pv[ii].w*vv[3].w;
            }
        }
        __syncthreads();
    }

    // epilogue: normalize and write ctx[n, h*64+d]
#pragma unroll
    for (int i = 0; i < 4; i++) {
        const float inv = 1.0f / l[i];
        float4 r = make_float4(o[i][0]*inv, o[i][1]*inv, o[i][2]*inv, o[i][3]*inv);
        *(float4*)(ctx + ((size_t)(b * SEQ + (qt << 6) + i0 + i)) * DM + (h << 6) + c0) = r;
    }
}

// =======================================================================
// LayerNorm over rows of 512. 128 threads, one row per block.
// =======================================================================
__global__ void ln_kernel(const float* __restrict__ X, const float* __restrict__ gam,
                          const float* __restrict__ bet, float* __restrict__ out)
{
    __shared__ float red[2][4];
    const int row = blockIdx.x;
    const int tid = threadIdx.x;
    const float4 v = ((const float4*)(X + (size_t)row * DM))[tid];
    float s = v.x + v.y + v.z + v.w;
    float q = v.x*v.x + v.y*v.y + v.z*v.z + v.w*v.w;
#pragma unroll
    for (int off = 16; off > 0; off >>= 1) {
        s += __shfl_xor_sync(0xffffffffu, s, off);
        q += __shfl_xor_sync(0xffffffffu, q, off);
    }
    const int w = tid >> 5;
    if ((tid & 31) == 0) { red[0][w] = s; red[1][w] = q; }
    __syncthreads();
    s = red[0][0] + red[0][1] + red[0][2] + red[0][3];
    q = red[1][0] + red[1][1] + red[1][2] + red[1][3];
    const float mu  = s * (1.0f / 512.0f);
    const float var = q * (1.0f / 512.0f) - mu * mu;
    const float rs  = rsqrtf(var + 1e-5f);
    const float4 g4 = ((const float4*)gam)[tid];
    const float4 b4 = ((const float4*)bet)[tid];
    float4 r;
    r.x = (v.x - mu) * rs * g4.x + b4.x;
    r.y = (v.y - mu) * rs * g4.y + b4.y;
    r.z = (v.z - mu) * rs * g4.z + b4.z;
    r.w = (v.w - mu) * rs * g4.w + b4.w;
    ((float4*)(out + (size_t)row * DM))[tid] = r;
}

// =======================================================================
extern "C" void kernel_launch(void* const* d_in, const int* in_sizes, int n_in,
                              void* d_out, int out_size)
{
    const float* src  = (const float*)d_in[0];
    const float* mask = (const float*)d_in[1];
    const float* Wq = (const float*)d_in[2];  const float* bq = (const float*)d_in[3];
    const float* Wk = (const float*)d_in[4];  const float* bk = (const float*)d_in[5];
    const float* Wv = (const float*)d_in[6];  const float* bv = (const float*)d_in[7];
    const float* Wo = (const float*)d_in[8];  const float* bo = (const float*)d_in[9];
    const float* W1 = (const float*)d_in[10]; const float* b1 = (const float*)d_in[11];
    const float* W2 = (const float*)d_in[12]; const float* b2 = (const float*)d_in[13];
    const float* g1 = (const float*)d_in[14]; const float* be1 = (const float*)d_in[15];
    const float* g2 = (const float*)d_in[16]; const float* be2 = (const float*)d_in[17];

    float *Qp, *Kp, *Vp, *Cp, *Yp, *X1p, *Hp;
    cudaGetSymbolAddress((void**)&Qp,  g_Q);
    cudaGetSymbolAddress((void**)&Kp,  g_K);
    cudaGetSymbolAddress((void**)&Vp,  g_V);
    cudaGetSymbolAddress((void**)&Cp,  g_C);
    cudaGetSymbolAddress((void**)&Yp,  g_Y);
    cudaGetSymbolAddress((void**)&X1p, g_X1);
    cudaGetSymbolAddress((void**)&Hp,  g_H);

    const dim3 blk(256);
    const dim3 gq(DM / 128, NR / 128);      // (4, 64)
    const dim3 gf1(DFF / 128, NR / 128);    // (16, 64)

    // QKV projections (scatter into [b,h,s,d])
    gemm_kernel<true><<<gq, blk>>>(src, Wq, bq, nullptr, Qp, NR, DM, DM, 0);
    gemm_kernel<true><<<gq, blk>>>(src, Wk, bk, nullptr, Kp, NR, DM, DM, 0);
    gemm_kernel<true><<<gq, blk>>>(src, Wv, bv, nullptr, Vp, NR, DM, DM, 0);

    // flash attention
    const size_t smBytes = 4 * 64 * 68 * sizeof(float);  // 69632 B
    cudaFuncSetAttribute(attn_kernel, cudaFuncAttributeMaxDynamicSharedMemorySize, (int)smBytes);
    const dim3 ga(NH, SEQ / 64, BATCH);     // head fastest -> mask L2 reuse
    attn_kernel<<<ga, blk, smBytes>>>(Qp, Kp, Vp, mask, Cp);

    // output projection + residual -> LN1
    gemm_kernel<false><<<gq, blk>>>(Cp, Wo, bo, src, Yp, NR, DM, DM, 0);
    ln_kernel<<<NR, 128>>>(Yp, g1, be1, X1p);

    // FFN
    gemm_kernel<false><<<gf1, blk>>>(X1p, W1, b1, nullptr, Hp, NR, DFF, DM, 1);
    gemm_kernel<false><<<gq,  blk>>>(Hp,  W2, b2, X1p,    Yp, NR, DM, DFF, 0);
    ln_kernel<<<NR, 128>>>(Yp, g2, be2, (float*)d_out);
}

// round 3
// speedup vs baseline: 2.1654x; 2.1654x over previous
#include <cuda_runtime.h>
#include <cuda_bf16.h>
#include <math.h>
#include <stdint.h>

#define DM   512
#define NH   8
#define HD   64
#define DFF  2048
#define BATCH 2
#define SEQ  4096
#define NR   (BATCH*SEQ)
#define NT   (SEQ/128)

// ---------------- scratch (device globals) ----------------
__device__ __nv_bfloat16 g_Qb[(size_t)BATCH*NH*SEQ*HD];   // [bh][s][d]
__device__ __nv_bfloat16 g_Kb[(size_t)BATCH*NH*SEQ*HD];   // [bh][s][d]
__device__ __nv_bfloat16 g_Vb[(size_t)BATCH*NH*SEQ*HD];   // [bh][s][d]
__device__ float g_C [(size_t)NR*DM];
__device__ float g_Y [(size_t)NR*DM];
__device__ float g_X1[(size_t)NR*DM];
__device__ float g_H [(size_t)NR*DFF];

// ======================= PTX helpers ==================================
__device__ __forceinline__ uint32_t smem_u32(const void* p) {
    uint32_t a;
    asm("{ .reg .u64 t; cvta.to.shared.u64 t, %1; cvt.u32.u64 %0, t; }" : "=r"(a) : "l"(p));
    return a;
}
__device__ __forceinline__ void cpa16(uint32_t dst, const void* src) {
    asm volatile("cp.async.cg.shared.global [%0], [%1], 16;" :: "r"(dst), "l"(src) : "memory");
}
__device__ __forceinline__ void cpa_commit() { asm volatile("cp.async.commit_group;" ::: "memory"); }
__device__ __forceinline__ void cpa_wait0()  { asm volatile("cp.async.wait_group 0;" ::: "memory"); }

__device__ __forceinline__ void ldsm4(uint32_t* r, uint32_t a) {
    asm volatile("ldmatrix.sync.aligned.m8n8.x4.shared.b16 {%0,%1,%2,%3}, [%4];"
        : "=r"(r[0]), "=r"(r[1]), "=r"(r[2]), "=r"(r[3]) : "r"(a));
}
__device__ __forceinline__ void ldsm4t(uint32_t* r, uint32_t a) {
    asm volatile("ldmatrix.sync.aligned.m8n8.x4.trans.shared.b16 {%0,%1,%2,%3}, [%4];"
        : "=r"(r[0]), "=r"(r[1]), "=r"(r[2]), "=r"(r[3]) : "r"(a));
}
// D(16x8,f32) += A(16x16,bf16) x B(16x8,bf16)
__device__ __forceinline__ void hmma(float* d, const uint32_t* a, const uint32_t* b) {
    asm("mma.sync.aligned.m16n8k16.row.col.f32.bf16.bf16.f32 "
        "{%0,%1,%2,%3}, {%4,%5,%6,%7}, {%8,%9}, {%0,%1,%2,%3};"
        : "+f"(d[0]), "+f"(d[1]), "+f"(d[2]), "+f"(d[3])
        : "r"(a[0]), "r"(a[1]), "r"(a[2]), "r"(a[3]), "r"(b[0]), "r"(b[1]));
}
__device__ __forceinline__ float ex2f(float x) { float y; asm("ex2.approx.ftz.f32 %0, %1;" : "=f"(y) : "f"(x)); return y; }
__device__ __forceinline__ uint32_t packbf(float lo, float hi) {
    uint32_t r; asm("cvt.rn.bf16x2.f32 %0, %1, %2;" : "=r"(r) : "f"(hi), "f"(lo)); return r;
}

// ======================= SIMT GEMM (fp32 / bf16-scatter epilogues) ============
// MODE 0: fp32 out [M,N]; MODE 1: bf16 out [bh][s][d]
template<int MODE>
__global__ __launch_bounds__(256, 2)
void gemm_kernel(const float* __restrict__ A, const float* __restrict__ Bw,
                 const float* __restrict__ bias, const float* __restrict__ add,
                 void* __restrict__ Cout, int M, int N, int K, int relu)
{
    __shared__ float As[2][16][132];
    __shared__ float Bs[2][16][132];

    const int tid = threadIdx.x;
    const int bm  = blockIdx.y << 7;
    const int bn  = blockIdx.x << 7;
    const int tr  = (tid >> 4) << 3;
    const int tc  = (tid & 15) << 3;
    const int row0 = tid >> 2;
    const int kq   = (tid & 3) << 2;

    const float* Ap0 = A  + (size_t)(bm + row0) * K + kq;
    const float* Ap1 = Ap0 + (size_t)64 * K;
    const float* Bp0 = Bw + (size_t)(bn + row0) * K + kq;
    const float* Bp1 = Bp0 + (size_t)64 * K;

    float acc[8][8];
#pragma unroll
    for (int i = 0; i < 8; i++)
#pragma unroll
        for (int j = 0; j < 8; j++) acc[i][j] = 0.f;

    float4 ra0 = *(const float4*)(Ap0);
    float4 ra1 = *(const float4*)(Ap1);
    float4 rb0 = *(const float4*)(Bp0);
    float4 rb1 = *(const float4*)(Bp1);

    const int KT = K >> 4;
    for (int kt = 0; kt < KT; kt++) {
        const int cur = kt & 1;
        As[cur][kq+0][row0]    = ra0.x; As[cur][kq+1][row0]    = ra0.y;
        As[cur][kq+2][row0]    = ra0.z; As[cur][kq+3][row0]    = ra0.w;
        As[cur][kq+0][row0+64] = ra1.x; As[cur][kq+1][row0+64] = ra1.y;
        As[cur][kq+2][row0+64] = ra1.z; As[cur][kq+3][row0+64] = ra1.w;
        Bs[cur][kq+0][row0]    = rb0.x; Bs[cur][kq+1][row0]    = rb0.y;
        Bs[cur][kq+2][row0]    = rb0.z; Bs[cur][kq+3][row0]    = rb0.w;
        Bs[cur][kq+0][row0+64] = rb1.x; Bs[cur][kq+1][row0+64] = rb1.y;
        Bs[cur][kq+2][row0+64] = rb1.z; Bs[cur][kq+3][row0+64] = rb1.w;
        __syncthreads();

        if (kt + 1 < KT) {
            const int off = (kt + 1) << 4;
            ra0 = *(const float4*)(Ap0 + off);
            ra1 = *(const float4*)(Ap1 + off);
            rb0 = *(const float4*)(Bp0 + off);
            rb1 = *(const float4*)(Bp1 + off);
        }

#pragma unroll
        for (int k = 0; k < 16; k++) {
            float4 A0 = *(const float4*)&As[cur][k][tr];
            float4 A1 = *(const float4*)&As[cur][k][tr+4];
            float4 B0 = *(const float4*)&Bs[cur][k][tc];
            float4 B1 = *(const float4*)&Bs[cur][k][tc+4];
            float av[8] = {A0.x,A0.y,A0.z,A0.w,A1.x,A1.y,A1.z,A1.w};
            float bv[8] = {B0.x,B0.y,B0.z,B0.w,B1.x,B1.y,B1.z,B1.w};
#pragma unroll
            for (int i = 0; i < 8; i++)
#pragma unroll
                for (int j = 0; j < 8; j++)
                    acc[i][j] += av[i] * bv[j];
        }
    }

#pragma unroll
    for (int i = 0; i < 8; i++) {
        const int gr = bm + tr + i;
#pragma unroll
        for (int j4 = 0; j4 < 2; j4++) {
            const int gc = bn + tc + (j4 << 2);
            float4 v;
            v.x = acc[i][j4*4+0] + bias[gc+0];
            v.y = acc[i][j4*4+1] + bias[gc+1];
            v.z = acc[i][j4*4+2] + bias[gc+2];
            v.w = acc[i][j4*4+3] + bias[gc+3];
            if (MODE == 0) {
                if (add) {
                    float4 ad = *(const float4*)(add + (size_t)gr * N + gc);
                    v.x += ad.x; v.y += ad.y; v.z += ad.z; v.w += ad.w;
                }
                if (relu) {
                    v.x = fmaxf(v.x, 0.f); v.y = fmaxf(v.y, 0.f);
                    v.z = fmaxf(v.z, 0.f); v.w = fmaxf(v.w, 0.f);
                }
                *(float4*)((float*)Cout + (size_t)gr * N + gc) = v;
            } else {
                const int bb = gr >> 12, s = gr & 4095, hh = gc >> 6, d = gc & 63;
                __nv_bfloat16* p = (__nv_bfloat16*)Cout + (((size_t)(bb*NH + hh)*SEQ + s) << 6) + d;
                *(__nv_bfloat162*)(p)     = __floats2bfloat162_rn(v.x, v.y);
                *(__nv_bfloat162*)(p + 2) = __floats2bfloat162_rn(v.z, v.w);
            }
        }
    }
}

// ======================= HMMA flash attention =========================
// CTA = 256 thr (8 warps), one (b,h,128-q-tile); warp w owns q-rows 16w..16w+15.
// K/V bf16 tiles 128x64, double-buffered, XOR-swizzled (16B chunk ^ (row&7)).
// No-max softmax: S frags -> exp -> bf16 A frags -> PV mma. O in registers.
#define SQ_OFF 0
#define SK_OFF 16384
#define SV_OFF 49152
#define ATT_SMEM 81920

__global__ __launch_bounds__(256, 2)
void attn_hmma_kernel(const __nv_bfloat16* __restrict__ Qb,
                      const __nv_bfloat16* __restrict__ Kb,
                      const __nv_bfloat16* __restrict__ Vb,
                      const float* __restrict__ mask,
                      float* __restrict__ ctx)
{
    extern __shared__ char smem[];
    const uint32_t sb = smem_u32(smem);
    const uint32_t sQ = sb + SQ_OFF, sK = sb + SK_OFF, sV = sb + SV_OFF;

    const int tid = threadIdx.x, w = tid >> 5, lane = tid & 31;
    const int h = blockIdx.x, qt = blockIdx.y, b = blockIdx.z;
    const int bh = b * NH + h;

    const char* Qg = (const char*)(Qb + ((size_t)bh * SEQ + ((size_t)qt << 7)) * HD);
    const char* Kg = (const char*)(Kb + (size_t)bh * SEQ * HD);
    const char* Vg = (const char*)(Vb + (size_t)bh * SEQ * HD);

    // per-thread tile-copy offsets (4 x 16B chunks per 16KB tile)
    uint32_t offS[4], offG[4];
#pragma unroll
    for (int u = 0; u < 4; u++) {
        const int idx = tid + (u << 8);
        const int r = idx >> 3, c = idx & 7;
        offG[u] = (uint32_t)(r * 128 + c * 16);
        offS[u] = (uint32_t)(r * 128 + ((c ^ (r & 7)) << 4));
    }

    // preload Q, K0, V0
#pragma unroll
    for (int u = 0; u < 4; u++) {
        cpa16(sQ + offS[u], Qg + offG[u]);
        cpa16(sK + offS[u], Kg + offG[u]);
        cpa16(sV + offS[u], Vg + offG[u]);
    }
    cpa_commit();
    cpa_wait0();
    __syncthreads();

    // ldmatrix per-lane offsets
    const int l7 = lane & 7, l15 = lane & 15, lh = lane >> 4, lq = lane >> 3;
    const uint32_t koff0 = (uint32_t)(l7 * 128 + ((lq ^ l7) << 4));
    const uint32_t koff1 = (uint32_t)(l7 * 128 + (((lq + 4) ^ l7) << 4));
    uint32_t voff[4];
#pragma unroll
    for (int d2 = 0; d2 < 4; d2++)
        voff[d2] = (uint32_t)(l15 * 128 + (((d2 * 2 + lh) ^ l7) << 4));

    // Q fragments (16 rows x 64 cols) for this warp
    uint32_t Qf[4][4];
#pragma unroll
    for (int kc = 0; kc < 4; kc++) {
        const uint32_t qa = sQ + (uint32_t)((w * 16 + l15) * 128 + (((kc * 2 + lh) ^ l7) << 4));
        ldsm4(Qf[kc], qa);
    }

    // mask row pointers
    const int r0 = (lane >> 2);
    const float* mrow0 = mask + (size_t)b * SEQ * SEQ + (size_t)((qt << 7) + w * 16 + r0) * SEQ;
    const float* mrow1 = mrow0 + (size_t)8 * SEQ;

    float O[8][4];
#pragma unroll
    for (int i = 0; i < 8; i++)
#pragma unroll
        for (int j = 0; j < 4; j++) O[i][j] = 0.f;
    float l0 = 0.f, l1 = 0.f;

    const float C1 = 0.18033688011112042f;       // 0.125 * log2(e)
    const float C2 = -1.4426950408889634e9f;     // -1e9  * log2(e)

    for (int kt = 0; kt < NT; kt++) {
        // prefetch next K/V tiles
        if (kt + 1 < NT) {
            const char* Kn = Kg + (size_t)(kt + 1) * 16384;
            const char* Vn = Vg + (size_t)(kt + 1) * 16384;
            const uint32_t dK = sK + ((kt + 1) & 1) * 16384;
            const uint32_t dV = sV + ((kt + 1) & 1) * 16384;
#pragma unroll
            for (int u = 0; u < 4; u++) {
                cpa16(dK + offS[u], Kn + offG[u]);
                cpa16(dV + offS[u], Vn + offG[u]);
            }
        }
        cpa_commit();

        const uint32_t kb_base = sK + (kt & 1) * 16384;
        const uint32_t vb_base = sV + (kt & 1) * 16384;

#pragma unroll
        for (int kb = 0; kb < 8; kb++) {
            // ---- S = Q K^T for the 16 keys of this kb (two 8-key n-blocks) ----
            float s0[4] = {0.f, 0.f, 0.f, 0.f};
            float s1[4] = {0.f, 0.f, 0.f, 0.f};
            uint32_t kf[4];
            const uint32_t kr0 = kb_base + (uint32_t)((2 * kb) << 10);
            const uint32_t kr1 = kr0 + 1024;
            ldsm4(kf, kr0 + koff0);  hmma(s0, Qf[0], kf + 0); hmma(s0, Qf[1], kf + 2);
            ldsm4(kf, kr0 + koff1);  hmma(s0, Qf[2], kf + 0); hmma(s0, Qf[3], kf + 2);
            ldsm4(kf, kr1 + koff0);  hmma(s1, Qf[0], kf + 0); hmma(s1, Qf[1], kf + 2);
            ldsm4(kf, kr1 + koff1);  hmma(s1, Qf[2], kf + 0); hmma(s1, Qf[3], kf + 2);

            // ---- mask + exp ----
            const int mc = (kt << 7) + (kb << 4) + ((lane & 3) << 1);
            const float2 ma = *(const float2*)(mrow0 + mc);
            const float2 mb = *(const float2*)(mrow0 + mc + 8);
            const float2 mcv = *(const float2*)(mrow1 + mc);
            const float2 md = *(const float2*)(mrow1 + mc + 8);
            s0[0] = ex2f(fmaf(s0[0], C1, (1.f - ma.x)  * C2));
            s0[1] = ex2f(fmaf(s0[1], C1, (1.f - ma.y)  * C2));
            s0[2] = ex2f(fmaf(s0[2], C1, (1.f - mcv.x) * C2));
            s0[3] = ex2f(fmaf(s0[3], C1, (1.f - mcv.y) * C2));
            s1[0] = ex2f(fmaf(s1[0], C1, (1.f - mb.x)  * C2));
            s1[1] = ex2f(fmaf(s1[1], C1, (1.f - mb.y)  * C2));
            s1[2] = ex2f(fmaf(s1[2], C1, (1.f - md.x)  * C2));
            s1[3] = ex2f(fmaf(s1[3], C1, (1.f - md.y)  * C2));
            l0 += (s0[0] + s0[1]) + (s1[0] + s1[1]);
            l1 += (s0[2] + s0[3]) + (s1[2] + s1[3]);

            // ---- pack P (C-frag -> A-frag identity) ----
            uint32_t a[4];
            a[0] = packbf(s0[0], s0[1]);
            a[1] = packbf(s0[2], s0[3]);
            a[2] = packbf(s1[0], s1[1]);
            a[3] = packbf(s1[2], s1[3]);

            // ---- O += P V ----
            const uint32_t vr = vb_base + (uint32_t)(kb << 11);
#pragma unroll
            for (int d2 = 0; d2 < 4; d2++) {
                uint32_t v[4];
                ldsm4t(v, vr + voff[d2]);
                hmma(O[d2 * 2],     a, v + 0);
                hmma(O[d2 * 2 + 1], a, v + 2);
            }
        }

        cpa_wait0();
        __syncthreads();
    }

    // ---- epilogue: row-sum reduce over the 4 lanes of each row ----
    l0 += __shfl_xor_sync(0xffffffffu, l0, 1);
    l0 += __shfl_xor_sync(0xffffffffu, l0, 2);
    l1 += __shfl_xor_sync(0xffffffffu, l1, 1);
    l1 += __shfl_xor_sync(0xffffffffu, l1, 2);
    const float inv0 = 1.0f / l0;
    const float inv1 = 1.0f / l1;

    const size_t grow0 = (size_t)(b * SEQ + (qt << 7) + w * 16 + r0);
    float* c0 = ctx + grow0 * DM + (h << 6) + ((lane & 3) << 1);
    float* c1 = c0 + (size_t)8 * DM;
#pragma unroll
    for (int nb = 0; nb < 8; nb++) {
        *(float2*)(c0 + nb * 8) = make_float2(O[nb][0] * inv0, O[nb][1] * inv0);
        *(float2*)(c1 + nb * 8) = make_float2(O[nb][2] * inv1, O[nb][3] * inv1);
    }
}

// ======================= LayerNorm =======================
__global__ void ln_kernel(const float* __restrict__ X, const float* __restrict__ gam,
                          const float* __restrict__ bet, float* __restrict__ out)
{
    __shared__ float red[2][4];
    const int row = blockIdx.x;
    const int tid = threadIdx.x;
    const float4 v = ((const float4*)(X + (size_t)row * DM))[tid];
    float s = v.x + v.y + v.z + v.w;
    float q = v.x*v.x + v.y*v.y + v.z*v.z + v.w*v.w;
#pragma unroll
    for (int off = 16; off > 0; off >>= 1) {
        s += __shfl_xor_sync(0xffffffffu, s, off);
        q += __shfl_xor_sync(0xffffffffu, q, off);
    }
    const int w = tid >> 5;
    if ((tid & 31) == 0) { red[0][w] = s; red[1][w] = q; }
    __syncthreads();
    s = red[0][0] + red[0][1] + red[0][2] + red[0][3];
    q = red[1][0] + red[1][1] + red[1][2] + red[1][3];
    const float mu  = s * (1.0f / 512.0f);
    const float var = q * (1.0f / 512.0f) - mu * mu;
    const float rs  = rsqrtf(var + 1e-5f);
    const float4 g4 = ((const float4*)gam)[tid];
    const float4 b4 = ((const float4*)bet)[tid];
    float4 r;
    r.x = (v.x - mu) * rs * g4.x + b4.x;
    r.y = (v.y - mu) * rs * g4.y + b4.y;
    r.z = (v.z - mu) * rs * g4.z + b4.z;
    r.w = (v.w - mu) * rs * g4.w + b4.w;
    ((float4*)(out + (size_t)row * DM))[tid] = r;
}

// ======================= launch =======================
extern "C" void kernel_launch(void* const* d_in, const int* in_sizes, int n_in,
                              void* d_out, int out_size)
{
    const float* src  = (const float*)d_in[0];
    const float* mask = (const float*)d_in[1];
    const float* Wq = (const float*)d_in[2];  const float* bq = (const float*)d_in[3];
    const float* Wk = (const float*)d_in[4];  const float* bk = (const float*)d_in[5];
    const float* Wv = (const float*)d_in[6];  const float* bv = (const float*)d_in[7];
    const float* Wo = (const float*)d_in[8];  const float* bo = (const float*)d_in[9];
    const float* W1 = (const float*)d_in[10]; const float* b1 = (const float*)d_in[11];
    const float* W2 = (const float*)d_in[12]; const float* b2 = (const float*)d_in[13];
    const float* g1 = (const float*)d_in[14]; const float* be1 = (const float*)d_in[15];
    const float* g2 = (const float*)d_in[16]; const float* be2 = (const float*)d_in[17];

    __nv_bfloat16 *Qp, *Kp, *Vp;
    float *Cp, *Yp, *X1p, *Hp;
    cudaGetSymbolAddress((void**)&Qp,  g_Qb);
    cudaGetSymbolAddress((void**)&Kp,  g_Kb);
    cudaGetSymbolAddress((void**)&Vp,  g_Vb);
    cudaGetSymbolAddress((void**)&Cp,  g_C);
    cudaGetSymbolAddress((void**)&Yp,  g_Y);
    cudaGetSymbolAddress((void**)&X1p, g_X1);
    cudaGetSymbolAddress((void**)&Hp,  g_H);

    const dim3 blk(256);
    const dim3 gq(DM / 128, NR / 128);
    const dim3 gf1(DFF / 128, NR / 128);

    // QKV projections -> bf16 [bh][s][d]
    gemm_kernel<1><<<gq, blk>>>(src, Wq, bq, nullptr, Qp, NR, DM, DM, 0);
    gemm_kernel<1><<<gq, blk>>>(src, Wk, bk, nullptr, Kp, NR, DM, DM, 0);
    gemm_kernel<1><<<gq, blk>>>(src, Wv, bv, nullptr, Vp, NR, DM, DM, 0);

    // HMMA flash attention
    cudaFuncSetAttribute(attn_hmma_kernel, cudaFuncAttributeMaxDynamicSharedMemorySize, ATT_SMEM);
    const dim3 ga(NH, SEQ / 128, BATCH);
    attn_hmma_kernel<<<ga, blk, ATT_SMEM>>>(Qp, Kp, Vp, mask, Cp);

    // output projection + residual -> LN1
    gemm_kernel<0><<<gq, blk>>>(Cp, Wo, bo, src, Yp, NR, DM, DM, 0);
    ln_kernel<<<NR, 128>>>(Yp, g1, be1, X1p);

    // FFN
    gemm_kernel<0><<<gf1, blk>>>(X1p, W1, b1, nullptr, Hp, NR, DFF, DM, 1);
    gemm_kernel<0><<<gq,  blk>>>(Hp,  W2, b2, X1p,     Yp, NR, DM, DFF, 0);
    ln_kernel<<<NR, 128>>>(Yp, g2, be2, (float*)d_out);
}

// round 4
// speedup vs baseline: 3.7373x; 1.7259x over previous
#include <cuda_runtime.h>
#include <cuda_bf16.h>
#include <math.h>
#include <stdint.h>

#define DM   512
#define NH   8
#define HD   64
#define DFF  2048
#define BATCH 2
#define SEQ  4096
#define NR   (BATCH*SEQ)
#define NT   (SEQ/128)

// ---------------- scratch (device globals) ----------------
__device__ __nv_bfloat16 g_Qb[(size_t)BATCH*NH*SEQ*HD];   // [bh][s][d]
__device__ __nv_bfloat16 g_Kb[(size_t)BATCH*NH*SEQ*HD];   // [bh][s][d]
__device__ __nv_bfloat16 g_Vb[(size_t)BATCH*NH*SEQ*HD];   // [bh][s][d]
__device__ float g_C [(size_t)NR*DM];
__device__ float g_Y [(size_t)NR*DM];
__device__ float g_X1[(size_t)NR*DM];
__device__ float g_H [(size_t)NR*DFF];

// ======================= PTX helpers ==================================
__device__ __forceinline__ uint32_t smem_u32(const void* p) {
    uint32_t a;
    asm("{ .reg .u64 t; cvta.to.shared.u64 t, %1; cvt.u32.u64 %0, t; }" : "=r"(a) : "l"(p));
    return a;
}
__device__ __forceinline__ void cpa16(uint32_t dst, const void* src) {
    asm volatile("cp.async.cg.shared.global [%0], [%1], 16;" :: "r"(dst), "l"(src) : "memory");
}
__device__ __forceinline__ void cpa_commit() { asm volatile("cp.async.commit_group;" ::: "memory"); }
__device__ __forceinline__ void cpa_wait0()  { asm volatile("cp.async.wait_group 0;" ::: "memory"); }

__device__ __forceinline__ void ldsm4(uint32_t* r, uint32_t a) {
    asm volatile("ldmatrix.sync.aligned.m8n8.x4.shared.b16 {%0,%1,%2,%3}, [%4];"
        : "=r"(r[0]), "=r"(r[1]), "=r"(r[2]), "=r"(r[3]) : "r"(a));
}
__device__ __forceinline__ void ldsm4t(uint32_t* r, uint32_t a) {
    asm volatile("ldmatrix.sync.aligned.m8n8.x4.trans.shared.b16 {%0,%1,%2,%3}, [%4];"
        : "=r"(r[0]), "=r"(r[1]), "=r"(r[2]), "=r"(r[3]) : "r"(a));
}
// D(16x8,f32) += A(16x16,bf16) x B(16x8,bf16)
__device__ __forceinline__ void hmma(float* d, const uint32_t* a, const uint32_t* b) {
    asm("mma.sync.aligned.m16n8k16.row.col.f32.bf16.bf16.f32 "
        "{%0,%1,%2,%3}, {%4,%5,%6,%7}, {%8,%9}, {%0,%1,%2,%3};"
        : "+f"(d[0]), "+f"(d[1]), "+f"(d[2]), "+f"(d[3])
        : "r"(a[0]), "r"(a[1]), "r"(a[2]), "r"(a[3]), "r"(b[0]), "r"(b[1]));
}
// D(16x8,f32) += A(16x8,tf32) x B(8x8,tf32)
__device__ __forceinline__ void mmatf(float* d, const uint32_t* a, const uint32_t* b) {
    asm("mma.sync.aligned.m16n8k8.row.col.f32.tf32.tf32.f32 "
        "{%0,%1,%2,%3}, {%4,%5,%6,%7}, {%8,%9}, {%0,%1,%2,%3};"
        : "+f"(d[0]), "+f"(d[1]), "+f"(d[2]), "+f"(d[3])
        : "r"(a[0]), "r"(a[1]), "r"(a[2]), "r"(a[3]), "r"(b[0]), "r"(b[1]));
}
__device__ __forceinline__ uint32_t f2tf32(float x) {
    uint32_t r; asm("cvt.rna.tf32.f32 %0, %1;" : "=r"(r) : "f"(x)); return r;
}
__device__ __forceinline__ float ex2f(float x) { float y; asm("ex2.approx.ftz.f32 %0, %1;" : "=f"(y) : "f"(x)); return y; }
__device__ __forceinline__ uint32_t packbf(float lo, float hi) {
    uint32_t r; asm("cvt.rn.bf16x2.f32 %0, %1, %2;" : "=r"(r) : "f"(hi), "f"(lo)); return r;
}

// ======================= tf32 HMMA GEMM ===============================
// C[M,N] = A[M,K] @ Bw[N,K]^T + bias (+add) (relu)
// 128x128 tile, BK=16, 256 thr; warp tile 64x32 (4x4 m16n8k8 blocks).
// Smem [k][136] tf32 words, column m ^ (((k>>2)&3)<<3): staging STS and
// fragment LDS are both bank-conflict-free (verified lane-by-lane).
// MODE 0: fp32 out [M,N] (+add/relu). MODE 1: bf16 out [bh][s][d].
template<int MODE>
__global__ __launch_bounds__(256, 2)
void gemm_tf32(const float* __restrict__ A, const float* __restrict__ Bw,
               const float* __restrict__ bias, const float* __restrict__ add,
               void* __restrict__ Cout, int M, int N, int K, int relu)
{
    __shared__ uint32_t As[2][16][136];
    __shared__ uint32_t Bs[2][16][136];

    const int tid = threadIdx.x;
    const int w = tid >> 5, lane = tid & 31;
    const int bm = blockIdx.y << 7;
    const int bn = blockIdx.x << 7;
    const int row0 = tid >> 2;          // 0..63
    const int kq   = (tid & 3) << 2;    // 0,4,8,12
    const int wm = (w >> 2) << 6;       // 0,64
    const int wn = (w & 3) << 5;        // 0,32,64,96
    const int fr = lane >> 2, fk = lane & 3;

    const float* Ap0 = A  + (size_t)(bm + row0) * K + kq;
    const float* Ap1 = Ap0 + (size_t)64 * K;
    const float* Bp0 = Bw + (size_t)(bn + row0) * K + kq;
    const float* Bp1 = Bp0 + (size_t)64 * K;

    float acc[4][4][4];
#pragma unroll
    for (int i = 0; i < 4; i++)
#pragma unroll
        for (int j = 0; j < 4; j++)
#pragma unroll
            for (int r = 0; r < 4; r++) acc[i][j][r] = 0.f;

    float4 ra0 = *(const float4*)(Ap0);
    float4 ra1 = *(const float4*)(Ap1);
    float4 rb0 = *(const float4*)(Bp0);
    float4 rb1 = *(const float4*)(Bp1);

    const int KT = K >> 4;
    for (int kt = 0; kt < KT; kt++) {
        const int cur = kt & 1;
        const int csw = ((kq >> 2) & 3) << 3;   // (kq+j)>>2 == kq>>2 for j<4
        {
            const float a0v[4] = {ra0.x, ra0.y, ra0.z, ra0.w};
            const float a1v[4] = {ra1.x, ra1.y, ra1.z, ra1.w};
            const float b0v[4] = {rb0.x, rb0.y, rb0.z, rb0.w};
            const float b1v[4] = {rb1.x, rb1.y, rb1.z, rb1.w};
#pragma unroll
            for (int j = 0; j < 4; j++) {
                const int k = kq + j;
                As[cur][k][row0        ^ csw] = f2tf32(a0v[j]);
                As[cur][k][(row0 + 64) ^ csw] = f2tf32(a1v[j]);
                Bs[cur][k][row0        ^ csw] = f2tf32(b0v[j]);
                Bs[cur][k][(row0 + 64) ^ csw] = f2tf32(b1v[j]);
            }
        }
        __syncthreads();

        if (kt + 1 < KT) {
            const int off = (kt + 1) << 4;
            ra0 = *(const float4*)(Ap0 + off);
            ra1 = *(const float4*)(Ap1 + off);
            rb0 = *(const float4*)(Bp0 + off);
            rb1 = *(const float4*)(Bp1 + off);
        }

#pragma unroll
        for (int ks = 0; ks < 2; ks++) {
            const int k0 = (ks << 3) + fk;
            const int k1 = k0 + 4;
            const int sw0 = ((k0 >> 2) & 3) << 3;
            const int sw1 = ((k1 >> 2) & 3) << 3;
            uint32_t af[4][4], bf[4][2];
#pragma unroll
            for (int mb = 0; mb < 4; mb++) {
                const int m = wm + (mb << 4) + fr;
                af[mb][0] = As[cur][k0][m       ^ sw0];
                af[mb][1] = As[cur][k0][(m + 8) ^ sw0];
                af[mb][2] = As[cur][k1][m       ^ sw1];
                af[mb][3] = As[cur][k1][(m + 8) ^ sw1];
            }
#pragma unroll
            for (int nb = 0; nb < 4; nb++) {
                const int n = wn + (nb << 3) + fr;
                bf[nb][0] = Bs[cur][k0][n ^ sw0];
                bf[nb][1] = Bs[cur][k1][n ^ sw1];
            }
#pragma unroll
            for (int mb = 0; mb < 4; mb++)
#pragma unroll
                for (int nb = 0; nb < 4; nb++)
                    mmatf(acc[mb][nb], af[mb], bf[nb]);
        }
        __syncthreads();
    }

    // ---- epilogue ----
#pragma unroll
    for (int mb = 0; mb < 4; mb++) {
        const int r0 = bm + wm + (mb << 4) + fr;
        const int r1 = r0 + 8;
#pragma unroll
        for (int nb = 0; nb < 4; nb++) {
            const int gc = bn + wn + (nb << 3) + (fk << 1);
            const float2 b2 = *(const float2*)(bias + gc);
            float2 v0 = make_float2(acc[mb][nb][0] + b2.x, acc[mb][nb][1] + b2.y);
            float2 v1 = make_float2(acc[mb][nb][2] + b2.x, acc[mb][nb][3] + b2.y);
            if (MODE == 0) {
                if (add) {
                    const float2 a0 = *(const float2*)(add + (size_t)r0 * N + gc);
                    const float2 a1 = *(const float2*)(add + (size_t)r1 * N + gc);
                    v0.x += a0.x; v0.y += a0.y; v1.x += a1.x; v1.y += a1.y;
                }
                if (relu) {
                    v0.x = fmaxf(v0.x, 0.f); v0.y = fmaxf(v0.y, 0.f);
                    v1.x = fmaxf(v1.x, 0.f); v1.y = fmaxf(v1.y, 0.f);
                }
                *(float2*)((float*)Cout + (size_t)r0 * N + gc) = v0;
                *(float2*)((float*)Cout + (size_t)r1 * N + gc) = v1;
            } else {
                const int hh = gc >> 6, d = gc & 63;
                __nv_bfloat16* Cb = (__nv_bfloat16*)Cout;
                {
                    const int bb = r0 >> 12, s = r0 & 4095;
                    *(__nv_bfloat162*)(Cb + (((size_t)(bb*NH + hh)*SEQ + s) << 6) + d) =
                        __floats2bfloat162_rn(v0.x, v0.y);
                }
                {
                    const int bb = r1 >> 12, s = r1 & 4095;
                    *(__nv_bfloat162*)(Cb + (((size_t)(bb*NH + hh)*SEQ + s) << 6) + d) =
                        __floats2bfloat162_rn(v1.x, v1.y);
                }
            }
        }
    }
}

// ======================= HMMA flash attention (unchanged) =============
#define SQ_OFF 0
#define SK_OFF 16384
#define SV_OFF 49152
#define ATT_SMEM 81920

__global__ __launch_bounds__(256, 2)
void attn_hmma_kernel(const __nv_bfloat16* __restrict__ Qb,
                      const __nv_bfloat16* __restrict__ Kb,
                      const __nv_bfloat16* __restrict__ Vb,
                      const float* __restrict__ mask,
                      float* __restrict__ ctx)
{
    extern __shared__ char smem[];
    const uint32_t sb = smem_u32(smem);
    const uint32_t sQ = sb + SQ_OFF, sK = sb + SK_OFF, sV = sb + SV_OFF;

    const int tid = threadIdx.x, w = tid >> 5, lane = tid & 31;
    const int h = blockIdx.x, qt = blockIdx.y, b = blockIdx.z;
    const int bh = b * NH + h;

    const char* Qg = (const char*)(Qb + ((size_t)bh * SEQ + ((size_t)qt << 7)) * HD);
    const char* Kg = (const char*)(Kb + (size_t)bh * SEQ * HD);
    const char* Vg = (const char*)(Vb + (size_t)bh * SEQ * HD);

    uint32_t offS[4], offG[4];
#pragma unroll
    for (int u = 0; u < 4; u++) {
        const int idx = tid + (u << 8);
        const int r = idx >> 3, c = idx & 7;
        offG[u] = (uint32_t)(r * 128 + c * 16);
        offS[u] = (uint32_t)(r * 128 + ((c ^ (r & 7)) << 4));
    }

#pragma unroll
    for (int u = 0; u < 4; u++) {
        cpa16(sQ + offS[u], Qg + offG[u]);
        cpa16(sK + offS[u], Kg + offG[u]);
        cpa16(sV + offS[u], Vg + offG[u]);
    }
    cpa_commit();
    cpa_wait0();
    __syncthreads();

    const int l7 = lane & 7, l15 = lane & 15, lh = lane >> 4, lq = lane >> 3;
    const uint32_t koff0 = (uint32_t)(l7 * 128 + ((lq ^ l7) << 4));
    const uint32_t koff1 = (uint32_t)(l7 * 128 + (((lq + 4) ^ l7) << 4));
    uint32_t voff[4];
#pragma unroll
    for (int d2 = 0; d2 < 4; d2++)
        voff[d2] = (uint32_t)(l15 * 128 + (((d2 * 2 + lh) ^ l7) << 4));

    uint32_t Qf[4][4];
#pragma unroll
    for (int kc = 0; kc < 4; kc++) {
        const uint32_t qa = sQ + (uint32_t)((w * 16 + l15) * 128 + (((kc * 2 + lh) ^ l7) << 4));
        ldsm4(Qf[kc], qa);
    }

    const int r0 = (lane >> 2);
    const float* mrow0 = mask + (size_t)b * SEQ * SEQ + (size_t)((qt << 7) + w * 16 + r0) * SEQ;
    const float* mrow1 = mrow0 + (size_t)8 * SEQ;

    float O[8][4];
#pragma unroll
    for (int i = 0; i < 8; i++)
#pragma unroll
        for (int j = 0; j < 4; j++) O[i][j] = 0.f;
    float l0 = 0.f, l1 = 0.f;

    const float C1 = 0.18033688011112042f;
    const float C2 = -1.4426950408889634e9f;

    for (int kt = 0; kt < NT; kt++) {
        if (kt + 1 < NT) {
            const char* Kn = Kg + (size_t)(kt + 1) * 16384;
            const char* Vn = Vg + (size_t)(kt + 1) * 16384;
            const uint32_t dK = sK + ((kt + 1) & 1) * 16384;
            const uint32_t dV = sV + ((kt + 1) & 1) * 16384;
#pragma unroll
            for (int u = 0; u < 4; u++) {
                cpa16(dK + offS[u], Kn + offG[u]);
                cpa16(dV + offS[u], Vn + offG[u]);
            }
        }
        cpa_commit();

        const uint32_t kb_base = sK + (kt & 1) * 16384;
        const uint32_t vb_base = sV + (kt & 1) * 16384;

#pragma unroll
        for (int kb = 0; kb < 8; kb++) {
            float s0[4] = {0.f, 0.f, 0.f, 0.f};
            float s1[4] = {0.f, 0.f, 0.f, 0.f};
            uint32_t kf[4];
            const uint32_t kr0 = kb_base + (uint32_t)((2 * kb) << 10);
            const uint32_t kr1 = kr0 + 1024;
            ldsm4(kf, kr0 + koff0);  hmma(s0, Qf[0], kf + 0); hmma(s0, Qf[1], kf + 2);
            ldsm4(kf, kr0 + koff1);  hmma(s0, Qf[2], kf + 0); hmma(s0, Qf[3], kf + 2);
            ldsm4(kf, kr1 + koff0);  hmma(s1, Qf[0], kf + 0); hmma(s1, Qf[1], kf + 2);
            ldsm4(kf, kr1 + koff1);  hmma(s1, Qf[2], kf + 0); hmma(s1, Qf[3], kf + 2);

            const int mc = (kt << 7) + (kb << 4) + ((lane & 3) << 1);
            const float2 ma = *(const float2*)(mrow0 + mc);
            const float2 mb = *(const float2*)(mrow0 + mc + 8);
            const float2 mcv = *(const float2*)(mrow1 + mc);
            const float2 md = *(const float2*)(mrow1 + mc + 8);
            s0[0] = ex2f(fmaf(s0[0], C1, (1.f - ma.x)  * C2));
            s0[1] = ex2f(fmaf(s0[1], C1, (1.f - ma.y)  * C2));
            s0[2] = ex2f(fmaf(s0[2], C1, (1.f - mcv.x) * C2));
            s0[3] = ex2f(fmaf(s0[3], C1, (1.f - mcv.y) * C2));
            s1[0] = ex2f(fmaf(s1[0], C1, (1.f - mb.x)  * C2));
            s1[1] = ex2f(fmaf(s1[1], C1, (1.f - mb.y)  * C2));
            s1[2] = ex2f(fmaf(s1[2], C1, (1.f - md.x)  * C2));
            s1[3] = ex2f(fmaf(s1[3], C1, (1.f - md.y)  * C2));
            l0 += (s0[0] + s0[1]) + (s1[0] + s1[1]);
            l1 += (s0[2] + s0[3]) + (s1[2] + s1[3]);

            uint32_t a[4];
            a[0] = packbf(s0[0], s0[1]);
            a[1] = packbf(s0[2], s0[3]);
            a[2] = packbf(s1[0], s1[1]);
            a[3] = packbf(s1[2], s1[3]);

            const uint32_t vr = vb_base + (uint32_t)(kb << 11);
#pragma unroll
            for (int d2 = 0; d2 < 4; d2++) {
                uint32_t v[4];
                ldsm4t(v, vr + voff[d2]);
                hmma(O[d2 * 2],     a, v + 0);
                hmma(O[d2 * 2 + 1], a, v + 2);
            }
        }

        cpa_wait0();
        __syncthreads();
    }

    l0 += __shfl_xor_sync(0xffffffffu, l0, 1);
    l0 += __shfl_xor_sync(0xffffffffu, l0, 2);
    l1 += __shfl_xor_sync(0xffffffffu, l1, 1);
    l1 += __shfl_xor_sync(0xffffffffu, l1, 2);
    const float inv0 = 1.0f / l0;
    const float inv1 = 1.0f / l1;

    const size_t grow0 = (size_t)(b * SEQ + (qt << 7) + w * 16 + r0);
    float* c0 = ctx + grow0 * DM + (h << 6) + ((lane & 3) << 1);
    float* c1 = c0 + (size_t)8 * DM;
#pragma unroll
    for (int nb = 0; nb < 8; nb++) {
        *(float2*)(c0 + nb * 8) = make_float2(O[nb][0] * inv0, O[nb][1] * inv0);
        *(float2*)(c1 + nb * 8) = make_float2(O[nb][2] * inv1, O[nb][3] * inv1);
    }
}

// ======================= LayerNorm =======================
__global__ void ln_kernel(const float* __restrict__ X, const float* __restrict__ gam,
                          const float* __restrict__ bet, float* __restrict__ out)
{
    __shared__ float red[2][4];
    const int row = blockIdx.x;
    const int tid = threadIdx.x;
    const float4 v = ((const float4*)(X + (size_t)row * DM))[tid];
    float s = v.x + v.y + v.z + v.w;
    float q = v.x*v.x + v.y*v.y + v.z*v.z + v.w*v.w;
#pragma unroll
    for (int off = 16; off > 0; off >>= 1) {
        s += __shfl_xor_sync(0xffffffffu, s, off);
        q += __shfl_xor_sync(0xffffffffu, q, off);
    }
    const int w = tid >> 5;
    if ((tid & 31) == 0) { red[0][w] = s; red[1][w] = q; }
    __syncthreads();
    s = red[0][0] + red[0][1] + red[0][2] + red[0][3];
    q = red[1][0] + red[1][1] + red[1][2] + red[1][3];
    const float mu  = s * (1.0f / 512.0f);
    const float var = q * (1.0f / 512.0f) - mu * mu;
    const float rs  = rsqrtf(var + 1e-5f);
    const float4 g4 = ((const float4*)gam)[tid];
    const float4 b4 = ((const float4*)bet)[tid];
    float4 r;
    r.x = (v.x - mu) * rs * g4.x + b4.x;
    r.y = (v.y - mu) * rs * g4.y + b4.y;
    r.z = (v.z - mu) * rs * g4.z + b4.z;
    r.w = (v.w - mu) * rs * g4.w + b4.w;
    ((float4*)(out + (size_t)row * DM))[tid] = r;
}

// ======================= launch =======================
extern "C" void kernel_launch(void* const* d_in, const int* in_sizes, int n_in,
                              void* d_out, int out_size)
{
    const float* src  = (const float*)d_in[0];
    const float* mask = (const float*)d_in[1];
    const float* Wq = (const float*)d_in[2];  const float* bq = (const float*)d_in[3];
    const float* Wk = (const float*)d_in[4];  const float* bk = (const float*)d_in[5];
    const float* Wv = (const float*)d_in[6];  const float* bv = (const float*)d_in[7];
    const float* Wo = (const float*)d_in[8];  const float* bo = (const float*)d_in[9];
    const float* W1 = (const float*)d_in[10]; const float* b1 = (const float*)d_in[11];
    const float* W2 = (const float*)d_in[12]; const float* b2 = (const float*)d_in[13];
    const float* g1 = (const float*)d_in[14]; const float* be1 = (const float*)d_in[15];
    const float* g2 = (const float*)d_in[16]; const float* be2 = (const float*)d_in[17];

    __nv_bfloat16 *Qp, *Kp, *Vp;
    float *Cp, *Yp, *X1p, *Hp;
    cudaGetSymbolAddress((void**)&Qp,  g_Qb);
    cudaGetSymbolAddress((void**)&Kp,  g_Kb);
    cudaGetSymbolAddress((void**)&Vp,  g_Vb);
    cudaGetSymbolAddress((void**)&Cp,  g_C);
    cudaGetSymbolAddress((void**)&Yp,  g_Y);
    cudaGetSymbolAddress((void**)&X1p, g_X1);
    cudaGetSymbolAddress((void**)&Hp,  g_H);

    const dim3 blk(256);
    const dim3 gq(DM / 128, NR / 128);      // (4, 64)
    const dim3 gf1(DFF / 128, NR / 128);    // (16, 64)

    // QKV projections -> bf16 [bh][s][d]  (tf32 tensor-core GEMMs)
    gemm_tf32<1><<<gq, blk>>>(src, Wq, bq, nullptr, Qp, NR, DM, DM, 0);
    gemm_tf32<1><<<gq, blk>>>(src, Wk, bk, nullptr, Kp, NR, DM, DM, 0);
    gemm_tf32<1><<<gq, blk>>>(src, Wv, bv, nullptr, Vp, NR, DM, DM, 0);

    // HMMA flash attention
    cudaFuncSetAttribute(attn_hmma_kernel, cudaFuncAttributeMaxDynamicSharedMemorySize, ATT_SMEM);
    const dim3 ga(NH, SEQ / 128, BATCH);
    attn_hmma_kernel<<<ga, blk, ATT_SMEM>>>(Qp, Kp, Vp, mask, Cp);

    // output projection + residual -> LN1
    gemm_tf32<0><<<gq, blk>>>(Cp, Wo, bo, src, Yp, NR, DM, DM, 0);
    ln_kernel<<<NR, 128>>>(Yp, g1, be1, X1p);

    // FFN
    gemm_tf32<0><<<gf1, blk>>>(X1p, W1, b1, nullptr, Hp, NR, DFF, DM, 1);
    gemm_tf32<0><<<gq,  blk>>>(Hp,  W2, b2, X1p,     Yp, NR, DM, DFF, 0);
    ln_kernel<<<NR, 128>>>(Yp, g2, be2, (float*)d_out);
}